// round 4
// baseline (speedup 1.0000x reference)
#include <cuda_runtime.h>
#include <cstdint>

#define D 128
#define MAX_N 50176
#define MAX_E 810000

__device__ float g_hs[(size_t)MAX_N * D];   // h * outdeg^-0.5
__device__ float g_agg[(size_t)MAX_N * D];  // gathered, pre-scaled by indeg^-1.5
__device__ int   g_outdeg[MAX_N];
__device__ int   g_indeg[MAX_N];
__device__ int   g_rowstart[MAX_N];
__device__ int   g_cursor[MAX_N];
__device__ int   g_elist[MAX_E];            // src | (dist << 20)

// ---------------------------------------------------------------------------
// 1: degree counts (coalesced, 1 thread / edge)
// ---------------------------------------------------------------------------
__global__ void degree_kernel(const int* __restrict__ src,
                              const int* __restrict__ dst, int E) {
    int e = blockIdx.x * blockDim.x + threadIdx.x;
    if (e < E) {
        atomicAdd(&g_outdeg[src[e]], 1);
        atomicAdd(&g_indeg[dst[e]], 1);
    }
}

// ---------------------------------------------------------------------------
// 2: hs = h * outdeg^-0.5   (one float4 per thread)
// ---------------------------------------------------------------------------
__global__ void scale_h_kernel(const float* __restrict__ h, int N) {
    int idx = blockIdx.x * blockDim.x + threadIdx.x;   // over N * 32 float4s
    if (idx >= N * (D / 4)) return;
    int row = idx >> 5;
    float s = rsqrtf((float)g_indeg[0] * 0.f + (float)g_outdeg[row]); // rsqrt(outdeg)
    float4 v = reinterpret_cast<const float4*>(h)[idx];
    v.x *= s; v.y *= s; v.z *= s; v.w *= s;
    reinterpret_cast<float4*>(g_hs)[idx] = v;
}

// ---------------------------------------------------------------------------
// 3: exclusive scan of indeg -> rowstart (+ cursor copy).  Single block.
// ---------------------------------------------------------------------------
__global__ __launch_bounds__(1024)
void scan_kernel(int N) {
    const int T = 1024;
    int tid  = threadIdx.x;
    int per  = (N + T - 1) / T;
    int base = tid * per;

    int sum = 0;
    for (int i = 0; i < per; i++) {
        int idx = base + i;
        if (idx < N) sum += g_indeg[idx];
    }

    __shared__ int wsum[32];
    int lane = tid & 31, wid = tid >> 5;
    int inc = sum;
    #pragma unroll
    for (int o = 1; o < 32; o <<= 1) {
        int y = __shfl_up_sync(0xffffffffu, inc, o);
        if (lane >= o) inc += y;
    }
    if (lane == 31) wsum[wid] = inc;
    __syncthreads();
    if (wid == 0) {
        int v = wsum[lane];
        #pragma unroll
        for (int o = 1; o < 32; o <<= 1) {
            int y = __shfl_up_sync(0xffffffffu, v, o);
            if (lane >= o) v += y;
        }
        wsum[lane] = v;
    }
    __syncthreads();

    int run = inc - sum + (wid > 0 ? wsum[wid - 1] : 0);
    for (int i = 0; i < per; i++) {
        int idx = base + i;
        if (idx < N) {
            g_rowstart[idx] = run;
            g_cursor[idx]   = run;
            run += g_indeg[idx];
        }
    }
}

// ---------------------------------------------------------------------------
// 4: CSR fill: elist[pos] = src | dist<<20, grouped by dst
// ---------------------------------------------------------------------------
__global__ void fill_kernel(const int* __restrict__ src,
                            const int* __restrict__ dst,
                            const int* __restrict__ dist, int E) {
    int e = blockIdx.x * blockDim.x + threadIdx.x;
    if (e < E) {
        int pos = atomicAdd(&g_cursor[dst[e]], 1);
        g_elist[pos] = src[e] | (dist[e] << 20);
    }
}

// ---------------------------------------------------------------------------
// 5: gather: one warp per dst node; register accumulation, one store.
// g_agg[n] = indeg^-1.5 * sum_e hs[src_e] * 2^-dist_e
// ---------------------------------------------------------------------------
__global__ void gather_kernel(int N) {
    int gid  = blockIdx.x * blockDim.x + threadIdx.x;
    int n    = gid >> 5;
    int lane = gid & 31;
    if (n >= N) return;

    int start = g_rowstart[n];
    int deg   = g_indeg[n];

    const float4* hs4 = reinterpret_cast<const float4*>(g_hs);
    float4 acc = make_float4(0.f, 0.f, 0.f, 0.f);

    int k = 0;
    for (; k + 4 <= deg; k += 4) {
        int e0 = g_elist[start + k + 0];
        int e1 = g_elist[start + k + 1];
        int e2 = g_elist[start + k + 2];
        int e3 = g_elist[start + k + 3];
        float w0 = __int_as_float((127 - (e0 >> 20)) << 23);
        float w1 = __int_as_float((127 - (e1 >> 20)) << 23);
        float w2 = __int_as_float((127 - (e2 >> 20)) << 23);
        float w3 = __int_as_float((127 - (e3 >> 20)) << 23);
        float4 v0 = hs4[(size_t)(e0 & 0xFFFFF) * 32 + lane];
        float4 v1 = hs4[(size_t)(e1 & 0xFFFFF) * 32 + lane];
        float4 v2 = hs4[(size_t)(e2 & 0xFFFFF) * 32 + lane];
        float4 v3 = hs4[(size_t)(e3 & 0xFFFFF) * 32 + lane];
        acc.x = fmaf(v0.x, w0, acc.x); acc.y = fmaf(v0.y, w0, acc.y);
        acc.z = fmaf(v0.z, w0, acc.z); acc.w = fmaf(v0.w, w0, acc.w);
        acc.x = fmaf(v1.x, w1, acc.x); acc.y = fmaf(v1.y, w1, acc.y);
        acc.z = fmaf(v1.z, w1, acc.z); acc.w = fmaf(v1.w, w1, acc.w);
        acc.x = fmaf(v2.x, w2, acc.x); acc.y = fmaf(v2.y, w2, acc.y);
        acc.z = fmaf(v2.z, w2, acc.z); acc.w = fmaf(v2.w, w2, acc.w);
        acc.x = fmaf(v3.x, w3, acc.x); acc.y = fmaf(v3.y, w3, acc.y);
        acc.z = fmaf(v3.z, w3, acc.z); acc.w = fmaf(v3.w, w3, acc.w);
    }
    for (; k < deg; k++) {
        int e = g_elist[start + k];
        float w = __int_as_float((127 - (e >> 20)) << 23);
        float4 v = hs4[(size_t)(e & 0xFFFFF) * 32 + lane];
        acc.x = fmaf(v.x, w, acc.x); acc.y = fmaf(v.y, w, acc.y);
        acc.z = fmaf(v.z, w, acc.z); acc.w = fmaf(v.w, w, acc.w);
    }

    float id = (float)deg;
    float sc = rsqrtf(id) / id;                 // indeg^-1.5
    acc.x *= sc; acc.y *= sc; acc.z *= sc; acc.w *= sc;
    reinterpret_cast<float4*>(g_agg)[(size_t)n * 32 + lane] = acc;
}

// ---------------------------------------------------------------------------
// 6: out = g_agg @ W + bias   (A rows already fully scaled)
// ---------------------------------------------------------------------------
__global__ __launch_bounds__(256)
void gemm_kernel(const float* __restrict__ Wm, const float* __restrict__ bias,
                 float* __restrict__ out, int N) {
    extern __shared__ float sm[];
    float* As = sm;            // [k][m]
    float* Ws = sm + D * 128;  // [k][n]
    int tid  = threadIdx.x;
    int row0 = blockIdx.x * 128;

    for (int i = tid * 4; i < D * D; i += 256 * 4)
        *(float4*)(Ws + i) = *(const float4*)(Wm + i);

    for (int v = tid; v < 128 * (D / 4); v += 256) {
        int m  = v & 127;
        int k4 = (v >> 7) * 4;
        int grow = row0 + m;
        float4 a = make_float4(0.f, 0.f, 0.f, 0.f);
        if (grow < N)
            a = *(const float4*)(g_agg + (size_t)grow * D + k4);
        As[(k4 + 0) * 128 + m] = a.x;
        As[(k4 + 1) * 128 + m] = a.y;
        As[(k4 + 2) * 128 + m] = a.z;
        As[(k4 + 3) * 128 + m] = a.w;
    }
    __syncthreads();

    int tx = (tid & 15) * 8;
    int ty = (tid >> 4) * 8;

    float acc[8][8];
    #pragma unroll
    for (int i = 0; i < 8; i++)
        #pragma unroll
        for (int j = 0; j < 8; j++) acc[i][j] = 0.f;

    #pragma unroll 8
    for (int k = 0; k < D; k++) {
        float4 a0 = *(float4*)(As + k * 128 + ty);
        float4 a1 = *(float4*)(As + k * 128 + ty + 4);
        float4 b0 = *(float4*)(Ws + k * D + tx);
        float4 b1 = *(float4*)(Ws + k * D + tx + 4);
        float av[8] = {a0.x, a0.y, a0.z, a0.w, a1.x, a1.y, a1.z, a1.w};
        float bv[8] = {b0.x, b0.y, b0.z, b0.w, b1.x, b1.y, b1.z, b1.w};
        #pragma unroll
        for (int i = 0; i < 8; i++)
            #pragma unroll
            for (int j = 0; j < 8; j++)
                acc[i][j] = fmaf(av[i], bv[j], acc[i][j]);
    }

    float4 bb0 = *(const float4*)(bias + tx);
    float4 bb1 = *(const float4*)(bias + tx + 4);
    float bv[8] = {bb0.x, bb0.y, bb0.z, bb0.w, bb1.x, bb1.y, bb1.z, bb1.w};

    #pragma unroll
    for (int i = 0; i < 8; i++) {
        int grow = row0 + ty + i;
        if (grow < N) {
            float4 o0 = make_float4(acc[i][0] + bv[0], acc[i][1] + bv[1],
                                    acc[i][2] + bv[2], acc[i][3] + bv[3]);
            float4 o1 = make_float4(acc[i][4] + bv[4], acc[i][5] + bv[5],
                                    acc[i][6] + bv[6], acc[i][7] + bv[7]);
            *(float4*)(out + (size_t)grow * D + tx)     = o0;
            *(float4*)(out + (size_t)grow * D + tx + 4) = o1;
        }
    }
}

// ---------------------------------------------------------------------------
extern "C" void kernel_launch(void* const* d_in, const int* in_sizes, int n_in,
                              void* d_out, int out_size) {
    const float* h    = (const float*)d_in[0];
    const int*   src  = (const int*)  d_in[1];
    const int*   dst  = (const int*)  d_in[2];
    const int*   dist = (const int*)  d_in[3];
    const float* W    = (const float*)d_in[4];
    const float* bias = (const float*)d_in[5];
    float*       out  = (float*)d_out;

    int N = in_sizes[0] / D;
    int E = in_sizes[1];

    void *od_p, *id_p;
    cudaGetSymbolAddress(&od_p, g_outdeg);
    cudaGetSymbolAddress(&id_p, g_indeg);
    cudaMemsetAsync(od_p, 0, N * sizeof(int));
    cudaMemsetAsync(id_p, 0, N * sizeof(int));

    degree_kernel<<<(E + 255) / 256, 256>>>(src, dst, E);
    scale_h_kernel<<<(N * 32 + 255) / 256, 256>>>(h, N);
    scan_kernel<<<1, 1024>>>(N);
    fill_kernel<<<(E + 255) / 256, 256>>>(src, dst, dist, E);
    gather_kernel<<<((long long)N * 32 + 255) / 256, 256>>>(N);

    int smem_bytes = 2 * D * 128 * sizeof(float);
    cudaFuncSetAttribute(gemm_kernel,
                         cudaFuncAttributeMaxDynamicSharedMemorySize, smem_bytes);
    gemm_kernel<<<(N + 127) / 128, 256, smem_bytes>>>(W, bias, out, N);
}

// round 5
// speedup vs baseline: 1.2252x; 1.2252x over previous
#include <cuda_runtime.h>
#include <cstdint>

#define D 128
#define MAX_N 50176
#define MAX_E 810000

__device__ float g_agg[(size_t)MAX_N * D];
__device__ int   g_outdeg[MAX_N];
__device__ int   g_indeg[MAX_N];

// ---------------------------------------------------------------------------
// 1: degree counts — int2-vectorized, 2 edges per thread
// ---------------------------------------------------------------------------
__global__ void degree_kernel(const int* __restrict__ src,
                              const int* __restrict__ dst, int E) {
    int i = blockIdx.x * blockDim.x + threadIdx.x;
    int e = i * 2;
    if (e + 1 < E) {
        int2 s2 = *reinterpret_cast<const int2*>(src + e);
        int2 d2 = *reinterpret_cast<const int2*>(dst + e);
        atomicAdd(&g_outdeg[s2.x], 1);
        atomicAdd(&g_outdeg[s2.y], 1);
        atomicAdd(&g_indeg[d2.x], 1);
        atomicAdd(&g_indeg[d2.y], 1);
    } else if (e < E) {
        atomicAdd(&g_outdeg[src[e]], 1);
        atomicAdd(&g_indeg[dst[e]], 1);
    }
}

// ---------------------------------------------------------------------------
// 2: edge scatter.  One warp per edge; each lane handles a float4.
// g_agg[dst] += h[src] * out_deg[src]^-0.5 * 0.5^distance
// ---------------------------------------------------------------------------
__global__ void scatter_kernel(const float* __restrict__ h,
                               const int* __restrict__ src,
                               const int* __restrict__ dst,
                               const int* __restrict__ dist, int E) {
    int gid  = blockIdx.x * blockDim.x + threadIdx.x;
    int e    = gid >> 5;
    int lane = gid & 31;
    if (e >= E) return;

    int s = __ldg(src + e);
    int d = __ldg(dst + e);

    // lane 0 computes the scalar edge weight; broadcast to the warp
    float scale = 0.f;
    if (lane == 0) {
        int di = __ldg(dist + e);
        // 0.5^di via exponent trick (exact, pure ALU)
        scale = rsqrtf((float)g_outdeg[s]) * __int_as_float((127 - di) << 23);
    }
    scale = __shfl_sync(0xffffffffu, scale, 0);

    float4 v = reinterpret_cast<const float4*>(h + (size_t)s * D)[lane];
    float x = v.x * scale, y = v.y * scale, z = v.z * scale, w = v.w * scale;

    float* p = g_agg + (size_t)d * D + lane * 4;
    asm volatile("red.global.add.v4.f32 [%0], {%1,%2,%3,%4};"
                 :: "l"(p), "f"(x), "f"(y), "f"(z), "f"(w)
                 : "memory");
}

// ---------------------------------------------------------------------------
// 3: out = (g_agg * in_deg^-1.5) @ W + bias
// 128-row tile / block, 256 threads, 8x8 microtile (4+4 column split to keep
// the B-operand LDS.128 phases inside one 128B window -> conflict-free).
// ---------------------------------------------------------------------------
__global__ __launch_bounds__(256)
void gemm_kernel(const float* __restrict__ Wm, const float* __restrict__ bias,
                 float* __restrict__ out, int N) {
    extern __shared__ float sm[];
    float* As = sm;            // [k][m] : D x 128, transposed
    float* Ws = sm + D * 128;  // [k][n] : D x D, row-major
    int tid  = threadIdx.x;
    int row0 = blockIdx.x * 128;

    // Load W tile (16384 floats, float4-vectorized)
    for (int i = tid * 4; i < D * D; i += 256 * 4)
        *(float4*)(Ws + i) = *(const float4*)(Wm + i);

    // Load A tile, scaled by in_deg^-1.5, stored transposed.
    for (int v = tid; v < 128 * (D / 4); v += 256) {
        int m  = v & 127;
        int k4 = (v >> 7) * 4;
        int grow = row0 + m;
        float4 a = make_float4(0.f, 0.f, 0.f, 0.f);
        float  s = 0.f;
        if (grow < N) {
            a = *(const float4*)(g_agg + (size_t)grow * D + k4);
            float id = (float)g_indeg[grow];
            s = rsqrtf(id) / id;     // id^-1.5
        }
        As[(k4 + 0) * 128 + m] = a.x * s;
        As[(k4 + 1) * 128 + m] = a.y * s;
        As[(k4 + 2) * 128 + m] = a.z * s;
        As[(k4 + 3) * 128 + m] = a.w * s;
    }
    __syncthreads();

    int tx4 = (tid & 15) * 4;  // first column block; second at tx4 + 64
    int ty  = (tid >> 4) * 8;  // 8 contiguous rows (A loads are broadcasts)

    float acc[8][8];
    #pragma unroll
    for (int i = 0; i < 8; i++)
        #pragma unroll
        for (int j = 0; j < 8; j++) acc[i][j] = 0.f;

    #pragma unroll 8
    for (int k = 0; k < D; k++) {
        float4 a0 = *(float4*)(As + k * 128 + ty);
        float4 a1 = *(float4*)(As + k * 128 + ty + 4);
        float4 b0 = *(float4*)(Ws + k * D + tx4);        // conflict-free phase
        float4 b1 = *(float4*)(Ws + k * D + tx4 + 64);   // conflict-free phase
        float av[8] = {a0.x, a0.y, a0.z, a0.w, a1.x, a1.y, a1.z, a1.w};
        float bv[8] = {b0.x, b0.y, b0.z, b0.w, b1.x, b1.y, b1.z, b1.w};
        #pragma unroll
        for (int i = 0; i < 8; i++)
            #pragma unroll
            for (int j = 0; j < 8; j++)
                acc[i][j] = fmaf(av[i], bv[j], acc[i][j]);
    }

    float4 bb0 = *(const float4*)(bias + tx4);
    float4 bb1 = *(const float4*)(bias + tx4 + 64);
    float bv[8] = {bb0.x, bb0.y, bb0.z, bb0.w, bb1.x, bb1.y, bb1.z, bb1.w};

    #pragma unroll
    for (int i = 0; i < 8; i++) {
        int grow = row0 + ty + i;
        if (grow < N) {
            float4 o0 = make_float4(acc[i][0] + bv[0], acc[i][1] + bv[1],
                                    acc[i][2] + bv[2], acc[i][3] + bv[3]);
            float4 o1 = make_float4(acc[i][4] + bv[4], acc[i][5] + bv[5],
                                    acc[i][6] + bv[6], acc[i][7] + bv[7]);
            *(float4*)(out + (size_t)grow * D + tx4)      = o0;
            *(float4*)(out + (size_t)grow * D + tx4 + 64) = o1;
        }
    }
}

// ---------------------------------------------------------------------------
extern "C" void kernel_launch(void* const* d_in, const int* in_sizes, int n_in,
                              void* d_out, int out_size) {
    const float* h    = (const float*)d_in[0];
    const int*   src  = (const int*)  d_in[1];
    const int*   dst  = (const int*)  d_in[2];
    const int*   dist = (const int*)  d_in[3];
    const float* W    = (const float*)d_in[4];
    const float* bias = (const float*)d_in[5];
    float*       out  = (float*)d_out;

    int N = in_sizes[0] / D;
    int E = in_sizes[1];

    void *agg_p, *od_p, *id_p;
    cudaGetSymbolAddress(&agg_p, g_agg);
    cudaGetSymbolAddress(&od_p,  g_outdeg);
    cudaGetSymbolAddress(&id_p,  g_indeg);
    cudaMemsetAsync(agg_p, 0, (size_t)N * D * sizeof(float));
    cudaMemsetAsync(od_p,  0, N * sizeof(int));
    cudaMemsetAsync(id_p,  0, N * sizeof(int));

    int dthreads = (E + 1) / 2;
    degree_kernel<<<(dthreads + 255) / 256, 256>>>(src, dst, E);

    long long sthreads = (long long)E * 32;
    scatter_kernel<<<(unsigned)((sthreads + 255) / 256), 256>>>(h, src, dst, dist, E);

    int smem_bytes = 2 * D * 128 * sizeof(float);  // 128 KB
    cudaFuncSetAttribute(gemm_kernel,
                         cudaFuncAttributeMaxDynamicSharedMemorySize, smem_bytes);
    gemm_kernel<<<(N + 127) / 128, 256, smem_bytes>>>(W, bias, out, N);
}

// round 8
// speedup vs baseline: 1.7120x; 1.3972x over previous
#include <cuda_runtime.h>
#include <cuda_fp16.h>
#include <cstdint>

#define D 128
#define MAX_N 50176
#define MAX_E 810000

__device__ __half g_hs[(size_t)MAX_N * D];     // half(h * outdeg^-0.5)
__device__ __half g_agg[(size_t)MAX_N * D];    // f16 atomic accumulator
__device__ int    g_outdeg[MAX_N];
__device__ int    g_indeg[MAX_N];

// ---------------------------------------------------------------------------
// 1: degree counts
// ---------------------------------------------------------------------------
__global__ void degree_kernel(const int* __restrict__ src,
                              const int* __restrict__ dst, int E) {
    int i = blockIdx.x * blockDim.x + threadIdx.x;
    int e = i * 2;
    if (e + 1 < E) {
        int2 s2 = *reinterpret_cast<const int2*>(src + e);
        int2 d2 = *reinterpret_cast<const int2*>(dst + e);
        atomicAdd(&g_outdeg[s2.x], 1);
        atomicAdd(&g_outdeg[s2.y], 1);
        atomicAdd(&g_indeg[d2.x], 1);
        atomicAdd(&g_indeg[d2.y], 1);
    } else if (e < E) {
        atomicAdd(&g_outdeg[src[e]], 1);
        atomicAdd(&g_indeg[dst[e]], 1);
    }
}

// ---------------------------------------------------------------------------
// 2: g_hs = half(h * outdeg^-0.5)   (8 floats per thread)
// ---------------------------------------------------------------------------
__global__ void scale_h_kernel(const float* __restrict__ h, int N) {
    int idx = blockIdx.x * blockDim.x + threadIdx.x;   // over N*16 groups of 8
    if (idx >= N * (D / 8)) return;
    int row = idx >> 4;
    float s = rsqrtf((float)g_outdeg[row]);
    const float4* hp = reinterpret_cast<const float4*>(h) + (size_t)idx * 2;
    float4 a = hp[0];
    float4 b = hp[1];
    __half2 packs[4];
    packs[0] = __floats2half2_rn(a.x * s, a.y * s);
    packs[1] = __floats2half2_rn(a.z * s, a.w * s);
    packs[2] = __floats2half2_rn(b.x * s, b.y * s);
    packs[3] = __floats2half2_rn(b.z * s, b.w * s);
    reinterpret_cast<uint4*>(g_hs)[idx] = *reinterpret_cast<uint4*>(packs);
}

// ---------------------------------------------------------------------------
// 3: edge scatter.  16 lanes per edge; each lane moves 8 halves (16B).
// g_agg[dst] += g_hs[src] * 0.5^distance      (f16x2 vector reduction)
// ---------------------------------------------------------------------------
__global__ void scatter_kernel(const int* __restrict__ src,
                               const int* __restrict__ dst,
                               const int* __restrict__ dist, int E) {
    int gid  = blockIdx.x * blockDim.x + threadIdx.x;
    int e    = gid >> 4;
    int lane = gid & 15;
    if (e >= E) return;

    int s  = __ldg(src + e);
    int d  = __ldg(dst + e);
    int di = __ldg(dist + e);

    float w = __int_as_float((127 - di) << 23);   // exact 0.5^di
    __half2 w2 = __float2half2_rn(w);

    uint4 v = reinterpret_cast<const uint4*>(g_hs + (size_t)s * D)[lane];
    __half2* hv = reinterpret_cast<__half2*>(&v);
    hv[0] = __hmul2(hv[0], w2);
    hv[1] = __hmul2(hv[1], w2);
    hv[2] = __hmul2(hv[2], w2);
    hv[3] = __hmul2(hv[3], w2);

    __half* p = g_agg + (size_t)d * D + lane * 8;
    asm volatile("red.global.add.noftz.v4.f16x2 [%0], {%1,%2,%3,%4};"
                 :: "l"(p), "r"(v.x), "r"(v.y), "r"(v.z), "r"(v.w)
                 : "memory");
}

// ---------------------------------------------------------------------------
// 4: out = (float(g_agg) * in_deg^-1.5) @ W + bias
// ---------------------------------------------------------------------------
__global__ __launch_bounds__(256)
void gemm_kernel(const float* __restrict__ Wm, const float* __restrict__ bias,
                 float* __restrict__ out, int N) {
    extern __shared__ float sm[];
    float* As = sm;            // [k][m] : D x 128, transposed
    float* Ws = sm + D * 128;  // [k][n] : D x D, row-major
    int tid  = threadIdx.x;
    int row0 = blockIdx.x * 128;

    for (int i = tid * 4; i < D * D; i += 256 * 4)
        *(float4*)(Ws + i) = *(const float4*)(Wm + i);

    // A tile: 8 halves per thread-iter, converted to f32, scaled, transposed
    for (int v = tid; v < 128 * (D / 8); v += 256) {
        int m  = v & 127;
        int k8 = (v >> 7) * 8;
        int grow = row0 + m;
        float vals[8] = {0, 0, 0, 0, 0, 0, 0, 0};
        if (grow < N) {
            uint4 raw = *reinterpret_cast<const uint4*>(g_agg + (size_t)grow * D + k8);
            const __half2* hp = reinterpret_cast<const __half2*>(&raw);
            float id = (float)g_indeg[grow];
            float s  = rsqrtf(id) / id;     // id^-1.5
            #pragma unroll
            for (int j = 0; j < 4; j++) {
                float2 f = __half22float2(hp[j]);
                vals[2 * j]     = f.x * s;
                vals[2 * j + 1] = f.y * s;
            }
        }
        #pragma unroll
        for (int j = 0; j < 8; j++)
            As[(k8 + j) * 128 + m] = vals[j];
    }
    __syncthreads();

    int tx4 = (tid & 15) * 4;  // columns tx4 and tx4+64 (conflict-free phases)
    int ty  = (tid >> 4) * 8;

    float acc[8][8];
    #pragma unroll
    for (int i = 0; i < 8; i++)
        #pragma unroll
        for (int j = 0; j < 8; j++) acc[i][j] = 0.f;

    #pragma unroll 8
    for (int k = 0; k < D; k++) {
        float4 a0 = *(float4*)(As + k * 128 + ty);
        float4 a1 = *(float4*)(As + k * 128 + ty + 4);
        float4 b0 = *(float4*)(Ws + k * D + tx4);
        float4 b1 = *(float4*)(Ws + k * D + tx4 + 64);
        float av[8] = {a0.x, a0.y, a0.z, a0.w, a1.x, a1.y, a1.z, a1.w};
        float bv[8] = {b0.x, b0.y, b0.z, b0.w, b1.x, b1.y, b1.z, b1.w};
        #pragma unroll
        for (int i = 0; i < 8; i++)
            #pragma unroll
            for (int j = 0; j < 8; j++)
                acc[i][j] = fmaf(av[i], bv[j], acc[i][j]);
    }

    float4 bb0 = *(const float4*)(bias + tx4);
    float4 bb1 = *(const float4*)(bias + tx4 + 64);
    float bv[8] = {bb0.x, bb0.y, bb0.z, bb0.w, bb1.x, bb1.y, bb1.z, bb1.w};

    #pragma unroll
    for (int i = 0; i < 8; i++) {
        int grow = row0 + ty + i;
        if (grow < N) {
            float4 o0 = make_float4(acc[i][0] + bv[0], acc[i][1] + bv[1],
                                    acc[i][2] + bv[2], acc[i][3] + bv[3]);
            float4 o1 = make_float4(acc[i][4] + bv[4], acc[i][5] + bv[5],
                                    acc[i][6] + bv[6], acc[i][7] + bv[7]);
            *(float4*)(out + (size_t)grow * D + tx4)      = o0;
            *(float4*)(out + (size_t)grow * D + tx4 + 64) = o1;
        }
    }
}

// ---------------------------------------------------------------------------
extern "C" void kernel_launch(void* const* d_in, const int* in_sizes, int n_in,
                              void* d_out, int out_size) {
    const float* h    = (const float*)d_in[0];
    const int*   src  = (const int*)  d_in[1];
    const int*   dst  = (const int*)  d_in[2];
    const int*   dist = (const int*)  d_in[3];
    const float* W    = (const float*)d_in[4];
    const float* bias = (const float*)d_in[5];
    float*       out  = (float*)d_out;

    int N = in_sizes[0] / D;
    int E = in_sizes[1];

    void *agg_p, *od_p, *id_p;
    cudaGetSymbolAddress(&agg_p, g_agg);
    cudaGetSymbolAddress(&od_p,  g_outdeg);
    cudaGetSymbolAddress(&id_p,  g_indeg);
    cudaMemsetAsync(agg_p, 0, (size_t)N * D * sizeof(__half));
    cudaMemsetAsync(od_p,  0, N * sizeof(int));
    cudaMemsetAsync(id_p,  0, N * sizeof(int));

    int dthreads = (E + 1) / 2;
    degree_kernel<<<(dthreads + 255) / 256, 256>>>(src, dst, E);

    scale_h_kernel<<<(N * (D / 8) + 255) / 256, 256>>>(h, N);

    long long sthreads = (long long)E * 16;
    scatter_kernel<<<(unsigned)((sthreads + 255) / 256), 256>>>(src, dst, dist, E);

    int smem_bytes = 2 * D * 128 * sizeof(float);  // 128 KB
    cudaFuncSetAttribute(gemm_kernel,
                         cudaFuncAttributeMaxDynamicSharedMemorySize, smem_bytes);
    gemm_kernel<<<(N + 127) / 128, 256, smem_bytes>>>(W, bias, out, N);
}

// round 9
// speedup vs baseline: 2.4882x; 1.4534x over previous
#include <cuda_runtime.h>
#include <cuda_fp16.h>
#include <cstdint>

#define D 128
#define MAX_N 50176
#define MAX_E 810000
#define ROWP (D + 8)           // padded half-row: 136 halves = 272B (conflict-free ldmatrix)

__device__ __half g_hs[(size_t)MAX_N * D];     // half(h * outdeg^-0.5)
__device__ __half g_agg[(size_t)MAX_N * D];    // f16 atomic accumulator
__device__ int    g_outdeg[MAX_N];
__device__ int    g_indeg[MAX_N];

// ---------------------------------------------------------------------------
// 1: degree counts
// ---------------------------------------------------------------------------
__global__ void degree_kernel(const int* __restrict__ src,
                              const int* __restrict__ dst, int E) {
    int i = blockIdx.x * blockDim.x + threadIdx.x;
    int e = i * 2;
    if (e + 1 < E) {
        int2 s2 = *reinterpret_cast<const int2*>(src + e);
        int2 d2 = *reinterpret_cast<const int2*>(dst + e);
        atomicAdd(&g_outdeg[s2.x], 1);
        atomicAdd(&g_outdeg[s2.y], 1);
        atomicAdd(&g_indeg[d2.x], 1);
        atomicAdd(&g_indeg[d2.y], 1);
    } else if (e < E) {
        atomicAdd(&g_outdeg[src[e]], 1);
        atomicAdd(&g_indeg[dst[e]], 1);
    }
}

// ---------------------------------------------------------------------------
// 2: g_hs = half(h * outdeg^-0.5)
// ---------------------------------------------------------------------------
__global__ void scale_h_kernel(const float* __restrict__ h, int N) {
    int idx = blockIdx.x * blockDim.x + threadIdx.x;   // over N*16 groups of 8
    if (idx >= N * (D / 8)) return;
    int row = idx >> 4;
    float s = rsqrtf((float)g_outdeg[row]);
    const float4* hp = reinterpret_cast<const float4*>(h) + (size_t)idx * 2;
    float4 a = hp[0];
    float4 b = hp[1];
    __half2 packs[4];
    packs[0] = __floats2half2_rn(a.x * s, a.y * s);
    packs[1] = __floats2half2_rn(a.z * s, a.w * s);
    packs[2] = __floats2half2_rn(b.x * s, b.y * s);
    packs[3] = __floats2half2_rn(b.z * s, b.w * s);
    reinterpret_cast<uint4*>(g_hs)[idx] = *reinterpret_cast<uint4*>(packs);
}

// ---------------------------------------------------------------------------
// 3: edge scatter, 16 lanes/edge, f16x2 vector reduction
// ---------------------------------------------------------------------------
__global__ void scatter_kernel(const int* __restrict__ src,
                               const int* __restrict__ dst,
                               const int* __restrict__ dist, int E) {
    int gid  = blockIdx.x * blockDim.x + threadIdx.x;
    int e    = gid >> 4;
    int lane = gid & 15;
    if (e >= E) return;

    int s  = __ldg(src + e);
    int d  = __ldg(dst + e);
    int di = __ldg(dist + e);

    float w = __int_as_float((127 - di) << 23);   // exact 0.5^di
    __half2 w2 = __float2half2_rn(w);

    uint4 v = reinterpret_cast<const uint4*>(g_hs + (size_t)s * D)[lane];
    __half2* hv = reinterpret_cast<__half2*>(&v);
    hv[0] = __hmul2(hv[0], w2);
    hv[1] = __hmul2(hv[1], w2);
    hv[2] = __hmul2(hv[2], w2);
    hv[3] = __hmul2(hv[3], w2);

    __half* p = g_agg + (size_t)d * D + lane * 8;
    asm volatile("red.global.add.noftz.v4.f16x2 [%0], {%1,%2,%3,%4};"
                 :: "l"(p), "r"(v.x), "r"(v.y), "r"(v.z), "r"(v.w)
                 : "memory");
}

// ---------------------------------------------------------------------------
// 4: tensor-core GEMM: out = (f32(g_agg) @ f16(W)) * indeg^-1.5 + bias
// 128-row tile, 8 warps x 16 rows, HMMA m16n8k16, f32 accum, scale in epilogue
// ---------------------------------------------------------------------------
__device__ __forceinline__ uint32_t smem_u32(const void* p) {
    return (uint32_t)__cvta_generic_to_shared(p);
}

__global__ __launch_bounds__(256)
void gemm_kernel(const float* __restrict__ Wm, const float* __restrict__ bias,
                 float* __restrict__ out, int N) {
    extern __shared__ __half sm[];
    __half* As = sm;                 // [128][ROWP]
    __half* Ws = sm + 128 * ROWP;    // [k][n] padded
    int tid  = threadIdx.x;
    int row0 = blockIdx.x * 128;

    // W -> f16 smem (each thread: 16 float4 = 64 floats)
    for (int i = tid; i < D * D / 4; i += 256) {
        int k  = i >> 5;
        int c4 = (i & 31) * 4;
        float4 w = *(const float4*)(Wm + k * D + c4);
        __half2 h0 = __floats2half2_rn(w.x, w.y);
        __half2 h1 = __floats2half2_rn(w.z, w.w);
        *(__half2*)(Ws + k * ROWP + c4)     = h0;
        *(__half2*)(Ws + k * ROWP + c4 + 2) = h1;
    }
    // A tile: raw f16 copy of g_agg rows (scale deferred to epilogue)
    for (int i = tid; i < 128 * (D / 8); i += 256) {
        int m  = i >> 4;
        int c8 = (i & 15) * 8;
        int grow = row0 + m;
        uint4 v = make_uint4(0, 0, 0, 0);
        if (grow < N)
            v = *reinterpret_cast<const uint4*>(g_agg + (size_t)grow * D + c8);
        *reinterpret_cast<uint4*>(As + m * ROWP + c8) = v;
    }
    __syncthreads();

    int wid  = tid >> 5;
    int lane = tid & 31;
    int mrow = wid * 16;

    float acc[16][4];
    #pragma unroll
    for (int nb = 0; nb < 16; nb++)
        #pragma unroll
        for (int j = 0; j < 4; j++) acc[nb][j] = 0.f;

    uint32_t As_u = smem_u32(As);
    uint32_t Ws_u = smem_u32(Ws);
    int lr = lane & 15;
    int lc = (lane >> 4) << 3;

    #pragma unroll
    for (int kk = 0; kk < 8; kk++) {
        uint32_t a_addr = As_u + (uint32_t)(((mrow + lr) * ROWP) + kk * 16 + lc) * 2;
        uint32_t a0, a1, a2, a3;
        asm volatile("ldmatrix.sync.aligned.m8n8.x4.shared.b16 {%0,%1,%2,%3}, [%4];"
                     : "=r"(a0), "=r"(a1), "=r"(a2), "=r"(a3) : "r"(a_addr));
        #pragma unroll
        for (int nb = 0; nb < 16; nb++) {
            uint32_t b_addr = Ws_u + (uint32_t)(((kk * 16 + lr) * ROWP) + nb * 8) * 2;
            uint32_t b0, b1;
            asm volatile("ldmatrix.sync.aligned.m8n8.x2.trans.shared.b16 {%0,%1}, [%2];"
                         : "=r"(b0), "=r"(b1) : "r"(b_addr));
            asm volatile("mma.sync.aligned.m16n8k16.row.col.f32.f16.f16.f32 "
                         "{%0,%1,%2,%3},{%4,%5,%6,%7},{%8,%9},{%0,%1,%2,%3};"
                         : "+f"(acc[nb][0]), "+f"(acc[nb][1]),
                           "+f"(acc[nb][2]), "+f"(acc[nb][3])
                         : "r"(a0), "r"(a1), "r"(a2), "r"(a3), "r"(b0), "r"(b1));
        }
    }

    // epilogue: per-row indeg^-1.5 scale + bias
    int r0 = row0 + mrow + (lane >> 2);
    int r1 = r0 + 8;
    float s0 = 0.f, s1 = 0.f;
    if (r0 < N) { float id = (float)g_indeg[r0]; s0 = rsqrtf(id) / id; }
    if (r1 < N) { float id = (float)g_indeg[r1]; s1 = rsqrtf(id) / id; }

    #pragma unroll
    for (int nb = 0; nb < 16; nb++) {
        int col = nb * 8 + (lane & 3) * 2;
        float b0 = __ldg(bias + col);
        float b1 = __ldg(bias + col + 1);
        if (r0 < N) {
            float2 o = make_float2(acc[nb][0] * s0 + b0, acc[nb][1] * s0 + b1);
            *reinterpret_cast<float2*>(out + (size_t)r0 * D + col) = o;
        }
        if (r1 < N) {
            float2 o = make_float2(acc[nb][2] * s1 + b0, acc[nb][3] * s1 + b1);
            *reinterpret_cast<float2*>(out + (size_t)r1 * D + col) = o;
        }
    }
}

// ---------------------------------------------------------------------------
extern "C" void kernel_launch(void* const* d_in, const int* in_sizes, int n_in,
                              void* d_out, int out_size) {
    const float* h    = (const float*)d_in[0];
    const int*   src  = (const int*)  d_in[1];
    const int*   dst  = (const int*)  d_in[2];
    const int*   dist = (const int*)  d_in[3];
    const float* W    = (const float*)d_in[4];
    const float* bias = (const float*)d_in[5];
    float*       out  = (float*)d_out;

    int N = in_sizes[0] / D;
    int E = in_sizes[1];

    void *agg_p, *od_p, *id_p;
    cudaGetSymbolAddress(&agg_p, g_agg);
    cudaGetSymbolAddress(&od_p,  g_outdeg);
    cudaGetSymbolAddress(&id_p,  g_indeg);
    cudaMemsetAsync(agg_p, 0, (size_t)N * D * sizeof(__half));
    cudaMemsetAsync(od_p,  0, N * sizeof(int));
    cudaMemsetAsync(id_p,  0, N * sizeof(int));

    int dthreads = (E + 1) / 2;
    degree_kernel<<<(dthreads + 255) / 256, 256>>>(src, dst, E);

    scale_h_kernel<<<(N * (D / 8) + 255) / 256, 256>>>(h, N);

    long long sthreads = (long long)E * 16;
    scatter_kernel<<<(unsigned)((sthreads + 255) / 256), 256>>>(src, dst, dist, E);

    int smem_bytes = 2 * 128 * ROWP * sizeof(__half);  // ~68 KB
    cudaFuncSetAttribute(gemm_kernel,
                         cudaFuncAttributeMaxDynamicSharedMemorySize, smem_bytes);
    gemm_kernel<<<(N + 127) / 128, 256, smem_bytes>>>(W, bias, out, N);
}